// round 7
// baseline (speedup 1.0000x reference)
#include <cuda_runtime.h>

// Capsule dynamic routing, fused. x:[128,2048,8] W:[32,2048,16,8] out:[128,32,16]
// Identity: b_k[b,j,n] = (sum_{i<k} v_i) . u_hat[b,j,n]  ->  u_hat/b never stored.
// R7: one-time W-transpose ([j][n][i][p]) + x-duplication preps make the hot
// loop pure fma2 (no packs/adds); r=2 + 3 CTAs/SM for latency hiding.

#define BB 128
#define NN 2048
#define DD 8
#define JJ 32
#define PP 16
#define TPB 128

// pass1: BT=8 (r=2), pass0: BT=16 (r=4)
#define NC    64
#define NNT   32
#define NBT1  16
#define NBT0  8

#define WJS   132                      // W smem stride per j (4-bank skew)
#define WBUF  (JJ * WJS)               // 4224 floats per stage
#define XOFF  (3 * WBUF)               // 12672
#define XB1   (8 * 20)                 // x stage, pass1 (8 b, padded 20)
#define XB0   (16 * 20)                // x stage, pass0
#define EOFF1 (XOFF + 3 * XB1)         // 13152
#define SMEM1_B ((EOFF1 + 40) * 4)
#define SMEM0_B ((XOFF + 3 * XB0) * 4)

typedef unsigned long long u64;

__device__ __forceinline__ u64 fma2(u64 a, u64 b, u64 c) {
    u64 d; asm("fma.rn.f32x2 %0, %1, %2, %3;" : "=l"(d) : "l"(a), "l"(b), "l"(c));
    return d;
}
__device__ __forceinline__ u64 mul2(u64 a, u64 b) {
    u64 d; asm("mul.rn.f32x2 %0, %1, %2;" : "=l"(d) : "l"(a), "l"(b));
    return d;
}
__device__ __forceinline__ float lohi_add(u64 v) {
    float a, b; asm("mov.b64 {%0, %1}, %2;" : "=f"(a), "=f"(b) : "l"(v));
    return a + b;
}
__device__ __forceinline__ u64 scale2(u64 v, float s) {
    float a, b; asm("mov.b64 {%0, %1}, %2;" : "=f"(a), "=f"(b) : "l"(v));
    u64 d; asm("mov.b64 %0, {%1, %2};" : "=l"(d) : "f"(a * s), "f"(b * s));
    return d;
}
__device__ __forceinline__ unsigned smem_u32(const void* p) {
    return (unsigned)__cvta_generic_to_shared(p);
}
__device__ __forceinline__ void cp16(unsigned dst, const void* src) {
    asm volatile("cp.async.cg.shared.global [%0], [%1], 16;" :: "r"(dst), "l"(src));
}
__device__ __forceinline__ void cp_commit() { asm volatile("cp.async.commit_group;"); }
__device__ __forceinline__ void cp_wait1()  { asm volatile("cp.async.wait_group 1;"); }

__device__ __align__(16) float g_Wt[(size_t)JJ * NN * 128];   // [j][n][i*16+p]  32MB
__device__ __align__(16) float g_xd[(size_t)BB * NN * 16];    // [b][n][2i dup]  16MB
__device__ __align__(16) float g_part[(size_t)NNT * BB * JJ * PP];   // 8MB
__device__ __align__(16) float g_V[BB * JJ * PP];
__device__ float g_dummy;

__global__ void caps_dummy() { if (threadIdx.x == 0) g_dummy = 0.0f; }

// One-time: W[j][n][p][i] -> Wt[j][n][i][p]
__global__ void prep_W(const float* __restrict__ Wg)
{
    int idx = blockIdx.x * 256 + threadIdx.x;        // over 8.4M elems
    int jn = idx >> 7;
    int t  = idx & 127;                              // t = i*16 + p
    int i  = t >> 4, p = t & 15;
    g_Wt[idx] = Wg[(size_t)jn * 128 + p * 8 + i];
}
// One-time: x[b][n][i] -> xd[b][n][2i] duplicated pairs
__global__ void prep_x(const float* __restrict__ xg)
{
    int idx = blockIdx.x * 256 + threadIdx.x;        // over 4.2M elems
    int bn = idx >> 4;
    int k  = idx & 15;
    g_xd[idx] = xg[(size_t)bn * 8 + (k >> 1)];
}

// W stage: 1024 16B chunks; thread q-loop covers j = tid>>5 + 4q
__device__ __forceinline__ void stage_W(unsigned smW, int buf, int n, int tid)
{
    const int jb = tid >> 5, cc = tid & 31;
    const float* src = g_Wt + ((size_t)jb * NN + n) * 128 + cc * 4;
    unsigned dst = smW + (unsigned)(buf * WBUF + jb * WJS + cc * 4) * 4;
    #pragma unroll
    for (int q = 0; q < 8; q++)
        cp16(dst + q * (4 * WJS * 4), src + (size_t)q * 4 * NN * 128);
}

// ============ pass 1: routed c = softmax_j(V . u_hat), r=2 ============
__global__ void __launch_bounds__(TPB, 3)
caps_pass1(int dummy)
{
    extern __shared__ __align__(16) float sm[];
    const unsigned sm0 = smem_u32(sm);
    float* e_sh = sm + EOFF1;

    const int tid  = threadIdx.x;
    const int bp   = tid & 3;
    const int j    = tid >> 2;
    const int lane = tid & 31;
    const int w    = tid >> 5;
    const int bt   = blockIdx.x & (NBT1 - 1);
    const int nt   = blockIdx.x >> 4;
    const int b0   = bt * 8;
    const int n0   = nt * NC;

    u64 V2[2][8];
    #pragma unroll
    for (int r = 0; r < 2; r++) {
        const ulonglong2* vp = reinterpret_cast<const ulonglong2*>(
            &g_V[((size_t)(b0 + bp + 4*r) * JJ + j) * PP]);
        #pragma unroll
        for (int q = 0; q < 4; q++) {
            ulonglong2 t = vp[q]; V2[r][2*q] = t.x; V2[r][2*q+1] = t.y;
        }
    }

    // prologue: stages n0, n0+1
    #pragma unroll
    for (int st = 0; st < 2; st++) {
        stage_W(sm0, st, n0 + st, tid);
        if (tid < 32) {
            int b = tid >> 2, h = tid & 3;
            cp16(sm0 + (unsigned)(XOFF + st * XB1 + b * 20 + h * 4) * 4,
                 g_xd + ((size_t)(b0 + b) * NN + (n0 + st)) * 16 + h * 4);
        }
        cp_commit();
    }

    u64 s2[2][8];
    #pragma unroll
    for (int r = 0; r < 2; r++)
        #pragma unroll
        for (int q = 0; q < 8; q++) s2[r][q] = 0ull;

    int cur = 0, pf = 2;
    for (int nn = 0; nn < NC; nn++) {
        cp_wait1();
        __syncthreads();
        if (nn + 2 < NC) {
            stage_W(sm0, pf, n0 + nn + 2, tid);
            if (tid < 32) {
                int b = tid >> 2, h = tid & 3;
                cp16(sm0 + (unsigned)(XOFF + pf * XB1 + b * 20 + h * 4) * 4,
                     g_xd + ((size_t)(b0 + b) * NN + (n0 + nn + 2)) * 16 + h * 4);
            }
            cp_commit();
        }

        const float* Wj   = sm + cur * WBUF + j * WJS;
        const float* xrow = sm + XOFF + cur * XB1;

        u64 u2[2][8];
        #pragma unroll
        for (int i = 0; i < 8; i++) {
            const ulonglong2* wr = reinterpret_cast<const ulonglong2*>(Wj + i * 16);
            ulonglong2 a0 = wr[0], a1 = wr[1], a2 = wr[2], a3 = wr[3];
            u64 w8[8] = {a0.x, a0.y, a1.x, a1.y, a2.x, a2.y, a3.x, a3.y};
            #pragma unroll
            for (int r = 0; r < 2; r++) {
                u64 xv = *reinterpret_cast<const u64*>(xrow + (bp + 4*r) * 20 + i * 2);
                if (i == 0) {
                    #pragma unroll
                    for (int q = 0; q < 8; q++) u2[r][q] = mul2(w8[q], xv);
                } else {
                    #pragma unroll
                    for (int q = 0; q < 8; q++) u2[r][q] = fma2(w8[q], xv, u2[r][q]);
                }
            }
        }

        float e[2];
        #pragma unroll
        for (int r = 0; r < 2; r++) {
            u64 la = mul2(V2[r][0], u2[r][0]);
            u64 lb = mul2(V2[r][1], u2[r][1]);
            la = fma2(V2[r][2], u2[r][2], la);
            lb = fma2(V2[r][3], u2[r][3], lb);
            la = fma2(V2[r][4], u2[r][4], la);
            lb = fma2(V2[r][5], u2[r][5], lb);
            la = fma2(V2[r][6], u2[r][6], la);
            lb = fma2(V2[r][7], u2[r][7], lb);
            e[r] = __expf(lohi_add(la) + lohi_add(lb));   // |logit| small: raw exp ok
        }

        // fold 8 j in-warp, then 4 warps via e_sh
        float f[2];
        #pragma unroll
        for (int r = 0; r < 2; r++) {
            float v = e[r];
            v += __shfl_xor_sync(0xffffffffu, v, 4);
            v += __shfl_xor_sync(0xffffffffu, v, 8);
            v += __shfl_xor_sync(0xffffffffu, v, 16);
            f[r] = v;
        }
        if (lane < 4) {
            e_sh[(lane + 0) * 4 + w] = f[0];
            e_sh[(lane + 4) * 4 + w] = f[1];
        }
        __syncthreads();
        #pragma unroll
        for (int r = 0; r < 2; r++) {
            float4 t = *reinterpret_cast<const float4*>(&e_sh[(bp + 4*r) * 4]);
            float c = e[r] * __frcp_rn((t.x + t.y) + (t.z + t.w));
            u64 c2; asm("mov.b64 %0, {%1, %1};" : "=l"(c2) : "f"(c));
            #pragma unroll
            for (int q = 0; q < 8; q++) s2[r][q] = fma2(c2, u2[r][q], s2[r][q]);
        }

        cur = (cur == 2) ? 0 : cur + 1;
        pf  = (pf  == 2) ? 0 : pf  + 1;
    }

    #pragma unroll
    for (int r = 0; r < 2; r++) {
        ulonglong2* dst = reinterpret_cast<ulonglong2*>(
            &g_part[(((size_t)nt * BB + b0 + bp + 4*r) * JJ + j) * PP]);
        #pragma unroll
        for (int q = 0; q < 4; q++) {
            ulonglong2 t; t.x = s2[r][2*q]; t.y = s2[r][2*q+1]; dst[q] = t;
        }
    }
}

// ============ pass 0: uniform c = 1/32, r=4 ============
__global__ void __launch_bounds__(TPB, 3)
caps_pass0(int dummy)
{
    extern __shared__ __align__(16) float sm[];
    const unsigned sm0 = smem_u32(sm);

    const int tid = threadIdx.x;
    const int bp  = tid & 3;
    const int j   = tid >> 2;
    const int bt  = blockIdx.x & (NBT0 - 1);
    const int nt  = blockIdx.x >> 3;
    const int b0  = bt * 16;
    const int n0  = nt * NC;

    #pragma unroll
    for (int st = 0; st < 2; st++) {
        stage_W(sm0, st, n0 + st, tid);
        if (tid < 64) {
            int b = tid >> 2, h = tid & 3;
            cp16(sm0 + (unsigned)(XOFF + st * XB0 + b * 20 + h * 4) * 4,
                 g_xd + ((size_t)(b0 + b) * NN + (n0 + st)) * 16 + h * 4);
        }
        cp_commit();
    }

    u64 s2[4][8];
    #pragma unroll
    for (int r = 0; r < 4; r++)
        #pragma unroll
        for (int q = 0; q < 8; q++) s2[r][q] = 0ull;

    int cur = 0, pf = 2;
    for (int nn = 0; nn < NC; nn++) {
        cp_wait1();
        __syncthreads();
        if (nn + 2 < NC) {
            stage_W(sm0, pf, n0 + nn + 2, tid);
            if (tid < 64) {
                int b = tid >> 2, h = tid & 3;
                cp16(sm0 + (unsigned)(XOFF + pf * XB0 + b * 20 + h * 4) * 4,
                     g_xd + ((size_t)(b0 + b) * NN + (n0 + nn + 2)) * 16 + h * 4);
            }
            cp_commit();
        }

        const float* Wj   = sm + cur * WBUF + j * WJS;
        const float* xrow = sm + XOFF + cur * XB0;

        #pragma unroll
        for (int i = 0; i < 8; i++) {
            const ulonglong2* wr = reinterpret_cast<const ulonglong2*>(Wj + i * 16);
            ulonglong2 a0 = wr[0], a1 = wr[1], a2 = wr[2], a3 = wr[3];
            u64 w8[8] = {a0.x, a0.y, a1.x, a1.y, a2.x, a2.y, a3.x, a3.y};
            #pragma unroll
            for (int r = 0; r < 4; r++) {
                u64 xv = *reinterpret_cast<const u64*>(xrow + (bp + 4*r) * 20 + i * 2);
                #pragma unroll
                for (int q = 0; q < 8; q++) s2[r][q] = fma2(w8[q], xv, s2[r][q]);
            }
        }

        cur = (cur == 2) ? 0 : cur + 1;
        pf  = (pf  == 2) ? 0 : pf  + 1;
    }

    const float inv = 1.0f / 32.0f;
    #pragma unroll
    for (int r = 0; r < 4; r++) {
        ulonglong2* dst = reinterpret_cast<ulonglong2*>(
            &g_part[(((size_t)nt * BB + b0 + bp + 4*r) * JJ + j) * PP]);
        #pragma unroll
        for (int q = 0; q < 4; q++) {
            ulonglong2 t;
            t.x = scale2(s2[r][2*q],   inv);
            t.y = scale2(s2[r][2*q+1], inv);
            dst[q] = t;
        }
    }
}

// Reduce partials over nt (4-way + shfl), squash, update V / write out.
__global__ void caps_squash(float* __restrict__ outg, int stage)
{
    int t    = blockIdx.x * blockDim.x + threadIdx.x;
    int quad = t & 3;
    int k    = (t >> 2) & 3;
    int vec  = t >> 4;
    if (vec >= BB * JJ) return;

    float4 acc = make_float4(0.f, 0.f, 0.f, 0.f);
    #pragma unroll
    for (int ntk = 0; ntk < NNT / 4; ntk++) {
        int nt = k * (NNT / 4) + ntk;
        float4 v = *reinterpret_cast<const float4*>(
            &g_part[((size_t)nt * BB * JJ + vec) * PP + quad * 4]);
        acc.x += v.x; acc.y += v.y; acc.z += v.z; acc.w += v.w;
    }
    #pragma unroll
    for (int m = 4; m <= 8; m <<= 1) {
        acc.x += __shfl_xor_sync(0xffffffffu, acc.x, m);
        acc.y += __shfl_xor_sync(0xffffffffu, acc.y, m);
        acc.z += __shfl_xor_sync(0xffffffffu, acc.z, m);
        acc.w += __shfl_xor_sync(0xffffffffu, acc.w, m);
    }

    float s2 = acc.x * acc.x + acc.y * acc.y + acc.z * acc.z + acc.w * acc.w;
    s2 += __shfl_xor_sync(0xffffffffu, s2, 1);
    s2 += __shfl_xor_sync(0xffffffffu, s2, 2);

    float scale = s2 / ((1.0f + s2) * sqrtf(s2 + 1e-7f));
    float4 v4 = make_float4(acc.x * scale, acc.y * scale,
                            acc.z * scale, acc.w * scale);

    if (k == 0) {
        if (stage == 2) {
            *reinterpret_cast<float4*>(&outg[vec * PP + quad * 4]) = v4;
        } else if (stage == 0) {
            *reinterpret_cast<float4*>(&g_V[vec * PP + quad * 4]) = v4;
        } else {
            float4 cur = *reinterpret_cast<const float4*>(&g_V[vec * PP + quad * 4]);
            cur.x += v4.x; cur.y += v4.y; cur.z += v4.z; cur.w += v4.w;
            *reinterpret_cast<float4*>(&g_V[vec * PP + quad * 4]) = cur;
        }
    }
}

extern "C" void kernel_launch(void* const* d_in, const int* in_sizes, int n_in,
                              void* d_out, int out_size)
{
    const float* x = (const float*)d_in[0];
    const float* W = (const float*)d_in[1];
    if (n_in >= 2 && in_sizes[0] > in_sizes[1]) {
        const float* tmp = x; x = W; W = tmp;
    }
    float* out = (float*)d_out;

    cudaFuncSetAttribute(caps_pass0,
        cudaFuncAttributeMaxDynamicSharedMemorySize, SMEM0_B);
    cudaFuncSetAttribute(caps_pass1,
        cudaFuncAttributeMaxDynamicSharedMemorySize, SMEM1_B);

    const int GRID0 = NBT0 * NNT;                    // 256
    const int GRID1 = NBT1 * NNT;                    // 512
    const int SQ_BLOCK = 256;
    const int SQ_GRID  = (BB * JJ * 16 + SQ_BLOCK - 1) / SQ_BLOCK;   // 128

    caps_dummy<<<1, 32>>>();                         // 1 (ncu -s 5: slot 6 = pass1)
    prep_W<<<(JJ * NN * 128) / 256, 256>>>(W);       // 2
    prep_x<<<(BB * NN * 16) / 256, 256>>>(x);        // 3
    caps_pass0<<<GRID0, TPB, SMEM0_B>>>(0);          // 4
    caps_squash<<<SQ_GRID, SQ_BLOCK>>>(out, 0);      // 5: V = v0
    caps_pass1<<<GRID1, TPB, SMEM1_B>>>(0);          // 6  <- profiled
    caps_squash<<<SQ_GRID, SQ_BLOCK>>>(out, 1);      // V += v1
    caps_pass1<<<GRID1, TPB, SMEM1_B>>>(0);
    caps_squash<<<SQ_GRID, SQ_BLOCK>>>(out, 2);      // out = squash(s2)
}